// round 8
// baseline (speedup 1.0000x reference)
#include <cuda_runtime.h>
#include <math.h>
#include <stdint.h>

#define NND 2048
#define NNE (NND*NND)

// ---------------- device scratch ----------------
__device__ float g_A0[4u*NNE];            // interleaved: float4 per (i,j), c fastest
__device__ float g_Wh[4*NND*64];
__device__ float g_s1[4*NND], g_s2[4*NND];
__device__ float g_Whout[NND*16];
__device__ float g_s1o[NND], g_s2o[NND];
__device__ float g_hp[NND*1024];
__device__ float g_u0[4*NND], g_w0[4*NND], g_il0[4];
__device__ float g_uh[16*NND], g_wh2[16*NND], g_ilh[16];
__device__ float g_uo[4*NND], g_wo[4*NND], g_ilo[4];
__device__ float g_mean[16], g_rstd[16];

#define OFF_RC0 0
#define OFF_RR0 (4*NND)
#define OFF_HC  (8*NND)
#define OFF_HR  (24*NND)
#define OFF_OC  (40*NND)
#define OFF_OR  (44*NND)
#define OFF_GS  (48*NND)
#define OFF_X2  (48*NND+256)
#define SMALL_TOTAL (48*NND+256+NND*16)
__device__ float g_small[SMALL_TOTAL];

__device__ __forceinline__ float wred(float v){
    v += __shfl_down_sync(0xffffffffu, v, 16);
    v += __shfl_down_sync(0xffffffffu, v, 8);
    v += __shfl_down_sync(0xffffffffu, v, 4);
    v += __shfl_down_sync(0xffffffffu, v, 2);
    v += __shfl_down_sync(0xffffffffu, v, 1);
    return v;
}
__device__ __forceinline__ float leaky(float x){ return x > 0.f ? x : 0.2f*x; }
__device__ __forceinline__ float elu1(float x){ return x > 0.f ? x : (expf(x)-1.f); }

// ---------------- zero ----------------
__global__ void k_zero(){
    int i = blockIdx.x*256 + threadIdx.x;
    if(i < SMALL_TOTAL) g_small[i] = 0.f;
}

// ---------------- Wh = X @ W_heads[h] ----------------
__global__ void k_wh(const float* __restrict__ X, const float* __restrict__ W){
    int h = blockIdx.y;
    int nb = blockIdx.x*4;
    int t = threadIdx.x;
    __shared__ float Xs[4][128];
    #pragma unroll
    for(int q=0;q<2;q++){
        int idx = t + q*256;
        Xs[idx>>7][idx&127] = X[(size_t)(nb + (idx>>7))*128 + (idx&127)];
    }
    __syncthreads();
    int nl = t>>6, f = t&63;
    float a = 0.f;
    #pragma unroll 16
    for(int k=0;k<128;k++)
        a = fmaf(Xs[nl][k], W[((size_t)h*128 + k)*64 + f], a);
    g_Wh[((size_t)h*NND + nb + nl)*64 + f] = a;
}

// ---------------- s1, s2 per head ----------------
__global__ void k_s12(const float* __restrict__ ah){
    int h = blockIdx.y;
    int n = blockIdx.x*256 + threadIdx.x;
    const float* w = &g_Wh[((size_t)h*NND + n)*64];
    float s1 = 0.f, s2 = 0.f;
    #pragma unroll 16
    for(int f=0;f<64;f++){
        float v = w[f];
        s1 = fmaf(v, ah[h*128 + f],      s1);
        s2 = fmaf(v, ah[h*128 + 64 + f], s2);
    }
    g_s1[h*NND + n] = s1;
    g_s2[h*NND + n] = s2;
}

// ---------------- raw ef sums: rows ----------------
__global__ void k_rawA(const float4* __restrict__ ef){
    __shared__ float rp[4][8][9];
    int t = threadIdx.x, w = t>>5;
    int i0 = blockIdx.x*8;
    for(int ii=0; ii<8; ii++){
        int i = i0 + ii;
        float a0=0.f,a1=0.f,a2=0.f,a3=0.f;
        #pragma unroll
        for(int jb=0;jb<8;jb++){
            float4 v = ef[(size_t)i*NND + jb*256 + t];
            a0+=v.x; a1+=v.y; a2+=v.z; a3+=v.w;
        }
        float r0=wred(a0), r1=wred(a1), r2=wred(a2), r3=wred(a3);
        if((t&31)==0){ rp[0][ii][w]=r0; rp[1][ii][w]=r1; rp[2][ii][w]=r2; rp[3][ii][w]=r3; }
    }
    __syncthreads();
    if(t < 32){
        int c = t>>3, ii = t&7;
        float s = 0.f;
        for(int q=0;q<8;q++) s += rp[c][ii][q];
        g_small[OFF_RR0 + c*NND + i0 + ii] = s;
    }
}

// ---------------- raw ef sums: cols ----------------
__global__ void k_rawB(const float4* __restrict__ ef){
    __shared__ float cs[8][4][33];
    int t = threadIdx.x;
    int jl = t&31, ig = t>>5;
    int j = blockIdx.x*32 + jl;
    int ibase = blockIdx.y*512 + ig*64;
    float a0=0.f,a1=0.f,a2=0.f,a3=0.f;
    for(int r=0;r<64;r++){
        float4 v = ef[(size_t)(ibase+r)*NND + j];
        a0+=v.x; a1+=v.y; a2+=v.z; a3+=v.w;
    }
    cs[ig][0][jl]=a0; cs[ig][1][jl]=a1; cs[ig][2][jl]=a2; cs[ig][3][jl]=a3;
    __syncthreads();
    if(t < 128){
        int c = t>>5, jj = t&31;
        float s = 0.f;
        for(int g=0;g<8;g++) s += cs[g][c][jj];
        atomicAdd(&g_small[OFF_RC0 + c*NND + blockIdx.x*32 + jj], s);
    }
}

// ---------------- dsn params from sums ----------------
__global__ void k_params(int mode){
    int ch = blockIdx.x, t = threadIdx.x;
    const float *rs, *cs; float *u, *w, *il;
    if(mode==0){ rs=g_small+OFF_RR0+ch*NND; cs=g_small+OFF_RC0+ch*NND; u=g_u0+ch*NND; w=g_w0+ch*NND; il=g_il0+ch; }
    else if(mode==1){ rs=g_small+OFF_HR+ch*NND; cs=g_small+OFF_HC+ch*NND; u=g_uh+ch*NND; w=g_wh2+ch*NND; il=g_ilh+ch; }
    else { rs=g_small+OFF_OR+ch*NND; cs=g_small+OFF_OC+ch*NND; u=g_uo+ch*NND; w=g_wo+ch*NND; il=g_ilo+ch; }
    __shared__ float smx[256], ssm[256];
    __shared__ float lamS, irS, ilS;
    float mx = -3.4e38f, sm = 0.f;
    #pragma unroll
    for(int q=0;q<8;q++){
        float a = rs[t + q*256]; mx = fmaxf(mx, a); sm += a;
        float b = cs[t + q*256]; mx = fmaxf(mx, b);
    }
    smx[t] = mx; ssm[t] = sm;
    __syncthreads();
    for(int s=128; s; s>>=1){
        if(t < s){ smx[t] = fmaxf(smx[t], smx[t+s]); ssm[t] += ssm[t+s]; }
        __syncthreads();
    }
    if(t==0){
        float lam = smx[0];
        float r = (float)NND*lam - ssm[0];
        lamS = lam; irS = 1.f/r; ilS = 1.f/lam;
        il[0] = ilS;
    }
    __syncthreads();
    float lam = lamS, ir = irS, ilv = ilS;
    #pragma unroll
    for(int q=0;q<8;q++){
        int i = t + q*256;
        u[i] = (lam - rs[i]) * ir;
        w[i] = (lam - cs[i]) * ilv;
    }
}

// ---------------- build A0 + head row sums (16 combos) ----------------
__global__ void k_headA(const float4* __restrict__ ef){
    __shared__ float rp[16][8][9];
    int t = threadIdx.x, w = t>>5;
    int i0 = blockIdx.x*8;
    float il0v[4];
    #pragma unroll
    for(int c=0;c<4;c++) il0v[c] = g_il0[c];
    for(int ii=0; ii<8; ii++){
        int i = i0 + ii;
        float s1v[4], u0v[4];
        #pragma unroll
        for(int h=0;h<4;h++) s1v[h] = g_s1[h*NND + i];
        #pragma unroll
        for(int c=0;c<4;c++) u0v[c] = g_u0[c*NND + i];
        float acc[16];
        #pragma unroll
        for(int k=0;k<16;k++) acc[k] = 0.f;
        #pragma unroll 2
        for(int jb=0;jb<8;jb++){
            int j = jb*256 + t;
            float4 tv = ef[(size_t)i*NND + j];
            float tt[4] = {tv.x, tv.y, tv.z, tv.w};
            float A[4];
            #pragma unroll
            for(int c=0;c<4;c++){
                float w0 = g_w0[c*NND + j];
                A[c] = tt[c] > 0.f ? fmaf(tt[c], il0v[c], u0v[c]*w0) : tt[c];
            }
            ((float4*)g_A0)[(size_t)i*NND + j] = make_float4(A[0],A[1],A[2],A[3]);
            float P = 1.f;
            #pragma unroll
            for(int h=0;h<4;h++){
                P *= leaky(s1v[h] + g_s2[h*NND + j]);
                #pragma unroll
                for(int c=0;c<4;c++) acc[h*4+c] += A[c]*P;
            }
        }
        #pragma unroll
        for(int k=0;k<16;k++){
            float r = wred(acc[k]);
            if((t&31)==0) rp[k][ii][w] = r;
        }
    }
    __syncthreads();
    if(t < 128){
        int k = t>>3, ii = t&7;
        float s = 0.f;
        for(int q=0;q<8;q++) s += rp[k][ii][q];
        g_small[OFF_HR + k*NND + i0 + ii] = s;
    }
}

// ---------------- head col sums ----------------
__global__ void k_headB(){
    __shared__ float cs[8][16][33];
    int t = threadIdx.x;
    int jl = t&31, ig = t>>5;
    int j = blockIdx.x*32 + jl;
    int ibase = blockIdx.y*512 + ig*64;
    float s2v[4];
    #pragma unroll
    for(int h=0;h<4;h++) s2v[h] = g_s2[h*NND + j];
    float acc[16];
    #pragma unroll
    for(int k=0;k<16;k++) acc[k] = 0.f;
    const float4* a4 = (const float4*)g_A0;
    for(int r=0;r<64;r++){
        int i = ibase + r;
        float4 Av = a4[(size_t)i*NND + j];
        float A[4] = {Av.x, Av.y, Av.z, Av.w};
        float P = 1.f;
        #pragma unroll
        for(int h=0;h<4;h++){
            P *= leaky(g_s1[h*NND + i] + s2v[h]);
            #pragma unroll
            for(int c=0;c<4;c++) acc[h*4+c] += A[c]*P;
        }
    }
    #pragma unroll
    for(int k=0;k<16;k++) cs[ig][k][jl] = acc[k];
    __syncthreads();
    #pragma unroll
    for(int q=0;q<2;q++){
        int idx = t + q*256;
        int k = idx>>5, jj = idx&31;
        float s = 0.f;
        for(int g=0;g<8;g++) s += cs[g][k][jj];
        atomicAdd(&g_small[OFF_HC + k*NND + blockIdx.x*32 + jj], s);
    }
}

// ---------------- per-head attention @ Wh ----------------
__global__ void __launch_bounds__(256,2) k_headmm(){
    int h = blockIdx.y;
    int n0 = blockIdx.x*32;
    int t = threadIdx.x;
    __shared__ float attS[4][32][33];
    __shared__ float whS[32][64];
    __shared__ float s1S[4][32], uS[4][32], ilS[4];
    if(t < 32){
        #pragma unroll
        for(int m=0;m<4;m++) s1S[m][t] = g_s1[m*NND + n0 + t];
        #pragma unroll
        for(int c=0;c<4;c++) uS[c][t] = g_uh[(h*4+c)*NND + n0 + t];
    }
    if(t < 4) ilS[t] = g_ilh[h*4 + t];
    float acc[4][8];
    #pragma unroll
    for(int a=0;a<4;a++)
        #pragma unroll
        for(int b=0;b<8;b++) acc[a][b] = 0.f;
    int c_ = t>>6, r_ = t&63, ni = r_>>3, f0 = (r_&7)*8;
    int bn = t>>3, bm4 = (t&7)*4;
    const float4* a4 = (const float4*)g_A0;
    __syncthreads();
    for(int mt=0; mt<64; mt++){
        int m0 = mt*32;
        {
            const float4* wsrc = (const float4*)(g_Wh + ((size_t)h*NND + m0)*64);
            ((float4*)whS)[t] = wsrc[t];
            ((float4*)whS)[t+256] = wsrc[t+256];
        }
        #pragma unroll
        for(int k=0;k<4;k++){
            int m = bm4 + k, mg = m0 + m;
            float4 Av = a4[(size_t)(n0+bn)*NND + mg];
            float A[4] = {Av.x, Av.y, Av.z, Av.w};
            float P = 1.f;
            #pragma unroll
            for(int mh=0; mh<4; mh++)
                if(mh <= h) P *= leaky(s1S[mh][bn] + g_s2[mh*NND + mg]);
            #pragma unroll
            for(int c=0;c<4;c++){
                float e = A[c]*P;
                float wv = g_wh2[(h*4+c)*NND + mg];
                attS[c][bn][m] = e > 0.f ? fmaf(e, ilS[c], uS[c][bn]*wv) : e;
            }
        }
        __syncthreads();
        #pragma unroll 8
        for(int m=0;m<32;m++){
            float4 w0 = *(const float4*)&whS[m][f0];
            float4 w1 = *(const float4*)&whS[m][f0+4];
            #pragma unroll
            for(int nn=0;nn<4;nn++){
                float a = attS[c_][ni*4+nn][m];
                acc[nn][0] = fmaf(a, w0.x, acc[nn][0]);
                acc[nn][1] = fmaf(a, w0.y, acc[nn][1]);
                acc[nn][2] = fmaf(a, w0.z, acc[nn][2]);
                acc[nn][3] = fmaf(a, w0.w, acc[nn][3]);
                acc[nn][4] = fmaf(a, w1.x, acc[nn][4]);
                acc[nn][5] = fmaf(a, w1.y, acc[nn][5]);
                acc[nn][6] = fmaf(a, w1.z, acc[nn][6]);
                acc[nn][7] = fmaf(a, w1.w, acc[nn][7]);
            }
        }
        __syncthreads();
    }
    #pragma unroll
    for(int nn=0;nn<4;nn++){
        float* dst = &g_hp[(size_t)(n0 + ni*4 + nn)*1024 + h*256 + c_*64 + f0];
        *(float4*)dst     = make_float4(acc[nn][0],acc[nn][1],acc[nn][2],acc[nn][3]);
        *(float4*)(dst+4) = make_float4(acc[nn][4],acc[nn][5],acc[nn][6],acc[nn][7]);
    }
}

// ---------------- Whout = elu(hp) @ W_out ----------------
__global__ void k_whout(const float* __restrict__ Wout){
    int n = blockIdx.x;
    int t = threadIdx.x;
    __shared__ float eS[1024];
    __shared__ float part[16][17];
    {
        float4 hv = ((const float4*)(g_hp + (size_t)n*1024))[t];
        eS[t*4+0] = elu1(hv.x);
        eS[t*4+1] = elu1(hv.y);
        eS[t*4+2] = elu1(hv.z);
        eS[t*4+3] = elu1(hv.w);
    }
    __syncthreads();
    int g = t&15, kg = t>>4;
    float s = 0.f;
    #pragma unroll 8
    for(int k=0;k<64;k++)
        s = fmaf(eS[kg*64+k], Wout[(size_t)(kg*64+k)*16 + g], s);
    part[kg][g] = s;
    __syncthreads();
    if(t < 16){
        float a = 0.f;
        for(int q=0;q<16;q++) a += part[q][t];
        g_Whout[n*16 + t] = a;
    }
}

__global__ void k_s12o(const float* __restrict__ aout){
    int n = blockIdx.x*256 + threadIdx.x;
    float s1 = 0.f, s2 = 0.f;
    #pragma unroll
    for(int g=0;g<16;g++){
        float v = g_Whout[n*16+g];
        s1 = fmaf(v, aout[g],    s1);
        s2 = fmaf(v, aout[16+g], s2);
    }
    g_s1o[n] = s1; g_s2o[n] = s2;
}

// ---------------- out-layer e: write edge_attr output + row sums ----------------
__global__ void k_outA(float* __restrict__ dout){
    __shared__ float rp[4][8][9];
    int t = threadIdx.x, w = t>>5;
    int i0 = blockIdx.x*8;
    float* eo = dout + 128;
    const float4* a4 = (const float4*)g_A0;
    for(int ii=0; ii<8; ii++){
        int i = i0 + ii;
        float s1v[4];
        #pragma unroll
        for(int h=0;h<4;h++) s1v[h] = g_s1[h*NND + i];
        float s1ov = g_s1o[i];
        float a0=0.f,a1=0.f,a2=0.f,a3=0.f;
        #pragma unroll 2
        for(int jb=0;jb<8;jb++){
            int j = jb*256 + t;
            float4 Av = a4[(size_t)i*NND + j];
            float P = 1.f;
            #pragma unroll
            for(int h=0;h<4;h++) P *= leaky(s1v[h] + g_s2[h*NND + j]);
            P *= leaky(s1ov + g_s2o[j]);
            float e0 = Av.x*P, e1 = Av.y*P, e2 = Av.z*P, e3 = Av.w*P;
            eo[0u*NNE + (size_t)i*NND + j] = e0;
            eo[1u*NNE + (size_t)i*NND + j] = e1;
            eo[2u*NNE + (size_t)i*NND + j] = e2;
            eo[3u*NNE + (size_t)i*NND + j] = e3;
            a0 += e0; a1 += e1; a2 += e2; a3 += e3;
        }
        float r0=wred(a0), r1=wred(a1), r2=wred(a2), r3=wred(a3);
        if((t&31)==0){ rp[0][ii][w]=r0; rp[1][ii][w]=r1; rp[2][ii][w]=r2; rp[3][ii][w]=r3; }
    }
    __syncthreads();
    if(t < 32){
        int c = t>>3, ii = t&7;
        float s = 0.f;
        for(int q=0;q<8;q++) s += rp[c][ii][q];
        g_small[OFF_OR + c*NND + i0 + ii] = s;
    }
}

// ---------------- out-layer col sums (reads stored e) ----------------
__global__ void k_outB(const float* __restrict__ dout){
    __shared__ float cs[8][4][33];
    int t = threadIdx.x;
    int jl = t&31, ig = t>>5;
    int j = blockIdx.x*32 + jl;
    int ibase = blockIdx.y*512 + ig*64;
    const float* eo = dout + 128;
    float acc[4] = {0.f,0.f,0.f,0.f};
    for(int r=0;r<64;r++){
        size_t base = (size_t)(ibase+r)*NND + j;
        #pragma unroll
        for(int c=0;c<4;c++) acc[c] += eo[(size_t)c*NNE + base];
    }
    #pragma unroll
    for(int c=0;c<4;c++) cs[ig][c][jl] = acc[c];
    __syncthreads();
    if(t < 128){
        int c = t>>5, jj = t&31;
        float s = 0.f;
        for(int g=0;g<8;g++) s += cs[g][c][jj];
        atomicAdd(&g_small[OFF_OC + c*NND + blockIdx.x*32 + jj], s);
    }
}

// ---------------- out-layer: x2 = sum_c att_o[c] @ Whout ----------------
__global__ void k_outmm(){
    int n0 = blockIdx.x*32;
    int kbase = blockIdx.y*512;
    int t = threadIdx.x;
    __shared__ float asS[32][33];
    __shared__ float woS[32][16];
    __shared__ float s1S[4][32], s1oS[32], uoS[4][32], iloS[4];
    if(t < 32){
        #pragma unroll
        for(int h=0;h<4;h++) s1S[h][t] = g_s1[h*NND + n0 + t];
        s1oS[t] = g_s1o[n0 + t];
        #pragma unroll
        for(int c=0;c<4;c++) uoS[c][t] = g_uo[c*NND + n0 + t];
    }
    if(t < 4) iloS[t] = g_ilo[t];
    int bn = t>>3, bm4 = (t&7)*4;
    int na = t>>3, gp = (t&7)*2;
    float acc0 = 0.f, acc1 = 0.f;
    const float4* a4 = (const float4*)g_A0;
    __syncthreads();
    for(int mt=0; mt<16; mt++){
        int m0 = kbase + mt*32;
        ((float*)woS)[t]       = g_Whout[(size_t)m0*16 + t];
        ((float*)woS)[t+256]   = g_Whout[(size_t)m0*16 + t + 256];
        #pragma unroll
        for(int k=0;k<4;k++){
            int m = bm4 + k, mg = m0 + m;
            float4 Av = a4[(size_t)(n0+bn)*NND + mg];
            float A[4] = {Av.x, Av.y, Av.z, Av.w};
            float P = 1.f;
            #pragma unroll
            for(int h=0;h<4;h++) P *= leaky(s1S[h][bn] + g_s2[h*NND + mg]);
            P *= leaky(s1oS[bn] + g_s2o[mg]);
            float s = 0.f;
            #pragma unroll
            for(int c=0;c<4;c++){
                float e = A[c]*P;
                float wv = g_wo[c*NND + mg];
                s += e > 0.f ? fmaf(e, iloS[c], uoS[c][bn]*wv) : e;
            }
            asS[bn][m] = s;
        }
        __syncthreads();
        #pragma unroll 8
        for(int m=0;m<32;m++){
            float a = asS[na][m];
            acc0 = fmaf(a, woS[m][gp],   acc0);
            acc1 = fmaf(a, woS[m][gp+1], acc1);
        }
        __syncthreads();
    }
    atomicAdd(&g_small[OFF_X2 + (n0+na)*16 + gp],   acc0);
    atomicAdd(&g_small[OFF_X2 + (n0+na)*16 + gp+1], acc1);
}

// ---------------- bn1 stats ----------------
__global__ void k_bn1stats(){
    int t = threadIdx.x;
    int col = t&15, rg = t>>4;
    float s = 0.f, ss = 0.f;
    for(int r=0;r<128;r++){
        float v = g_small[OFF_X2 + (rg*128 + r)*16 + col];
        s += v; ss += v*v;
    }
    __shared__ float S[16][17], SS[16][17];
    S[rg][col] = s; SS[rg][col] = ss;
    __syncthreads();
    if(t < 16){
        float a = 0.f, b = 0.f;
        for(int q=0;q<16;q++){ a += S[q][t]; b += SS[q][t]; }
        float m = a / (float)NND;
        float var = b / (float)NND - m*m;
        g_mean[t] = m;
        g_rstd[t] = rsqrtf(var + 1e-5f);
    }
}

// ---------------- per-node tail: bn1+elu, bs, MLP1, gate, segment sum ----------------
__global__ void k_tail1(const float* __restrict__ bn1g, const float* __restrict__ bn1b,
                        const float* __restrict__ bss, const float* __restrict__ bsh,
                        const float* __restrict__ m1w1, const float* __restrict__ m1b1,
                        const float* __restrict__ m1w2, const float* __restrict__ m1b2,
                        const int* __restrict__ gidx, const int* __restrict__ didx){
    int t = threadIdx.x;
    int w = t>>5, l = t&31;
    int n = blockIdx.x*8 + w;
    __shared__ float xsS[8][17], g1S[8][65];
    int di = didx[n];
    if(l < 16){
        float v = g_small[OFF_X2 + n*16 + l];
        float xb = elu1((v - g_mean[l]) * g_rstd[l] * bn1g[l] + bn1b[l]);
        float xs = xb * bss[di*16 + l] + bsh[di*16 + l];
        xsS[w][l] = fmaxf(xs, 0.f);
    }
    __syncwarp();
    float a0 = m1b1[l], a1 = m1b1[l+32];
    #pragma unroll
    for(int k=0;k<16;k++){
        float x = xsS[w][k];
        a0 = fmaf(x, m1w1[k*64 + l],      a0);
        a1 = fmaf(x, m1w1[k*64 + l + 32], a1);
    }
    g1S[w][l]    = fmaxf(a0, 0.f);
    g1S[w][l+32] = fmaxf(a1, 0.f);
    __syncwarp();
    float c0 = m1b2[l], c1 = m1b2[l+32];
    #pragma unroll 8
    for(int k=0;k<64;k++){
        float x = g1S[w][k];
        c0 = fmaf(x, m1w2[k*64 + l],      c0);
        c1 = fmaf(x, m1w2[k*64 + l + 32], c1);
    }
    float ns = c1 * (1.f / (1.f + expf(-c0)));
    atomicAdd(&g_small[OFF_GS + gidx[n]*32 + l], ns);
}

// ---------------- graph-level tail: MLP2 + bn2 -> d_out[0:128] ----------------
__global__ void k_tail2(const float* __restrict__ m2w1, const float* __restrict__ m2b1,
                        const float* __restrict__ m2w2, const float* __restrict__ m2b2,
                        const float* __restrict__ bn2g, const float* __restrict__ bn2b,
                        float* __restrict__ dout){
    int t = threadIdx.x;
    __shared__ float r1S[8][33], r2S[8][17];
    {
        int g = t>>5, j = t&31;
        float v = m2b1[j];
        #pragma unroll
        for(int k=0;k<32;k++)
            v = fmaf(g_small[OFF_GS + g*32 + k], m2w1[k*32 + j], v);
        r1S[g][j] = fmaxf(v, 0.f);
    }
    __syncthreads();
    if(t < 128){
        int g = t>>4, j = t&15;
        float v = m2b2[j];
        #pragma unroll
        for(int k=0;k<32;k++)
            v = fmaf(r1S[g][k], m2w2[k*16 + j], v);
        r2S[g][j] = v;
    }
    __syncthreads();
    if(t < 16){
        float m = 0.f;
        for(int g=0;g<8;g++) m += r2S[g][t];
        m *= 0.125f;
        float var = 0.f;
        for(int g=0;g<8;g++){ float d = r2S[g][t] - m; var += d*d; }
        var *= 0.125f;
        float rs = rsqrtf(var + 1e-5f);
        for(int g=0;g<8;g++)
            dout[g*16 + t] = (r2S[g][t] - m) * rs * bn2g[t] + bn2b[t];
    }
}

// ---------------- launch ----------------
extern "C" void kernel_launch(void* const* d_in, const int* in_sizes, int n_in,
                              void* d_out, int out_size) {
    const float* X      = (const float*)d_in[0];
    const float* ef     = (const float*)d_in[1];
    const float* Wheads = (const float*)d_in[2];
    const float* aheads = (const float*)d_in[3];
    const float* Wout   = (const float*)d_in[4];
    const float* aout   = (const float*)d_in[5];
    const float* bn1g   = (const float*)d_in[6];
    const float* bn1b   = (const float*)d_in[7];
    const float* bss    = (const float*)d_in[8];
    const float* bsh    = (const float*)d_in[9];
    const float* m1w1   = (const float*)d_in[10];
    const float* m1b1   = (const float*)d_in[11];
    const float* m1w2   = (const float*)d_in[12];
    const float* m1b2   = (const float*)d_in[13];
    const float* m2w1   = (const float*)d_in[14];
    const float* m2b1   = (const float*)d_in[15];
    const float* m2w2   = (const float*)d_in[16];
    const float* m2b2   = (const float*)d_in[17];
    const float* bn2g   = (const float*)d_in[18];
    const float* bn2b   = (const float*)d_in[19];
    const int*   gidx   = (const int*)d_in[20];
    const int*   didx   = (const int*)d_in[21];
    float* dout = (float*)d_out;
    (void)in_sizes; (void)n_in; (void)out_size;

    k_zero<<<(SMALL_TOTAL+255)/256, 256>>>();
    k_wh<<<dim3(512,4), 256>>>(X, Wheads);
    k_s12<<<dim3(8,4), 256>>>(aheads);
    k_rawA<<<256, 256>>>((const float4*)ef);
    k_rawB<<<dim3(64,4), 256>>>((const float4*)ef);
    k_params<<<4, 256>>>(0);
    k_headA<<<256, 256>>>((const float4*)ef);
    k_headB<<<dim3(64,4), 256>>>();
    k_params<<<16, 256>>>(1);
    k_headmm<<<dim3(64,4), 256>>>();
    k_whout<<<2048, 256>>>(Wout);
    k_s12o<<<8, 256>>>(aout);
    k_outA<<<256, 256>>>(dout);
    k_outB<<<dim3(64,4), 256>>>(dout);
    k_params<<<4, 256>>>(2);
    k_outmm<<<dim3(64,4), 256>>>();
    k_bn1stats<<<1, 256>>>();
    k_tail1<<<256, 256>>>(bn1g, bn1b, bss, bsh, m1w1, m1b1, m1w2, m1b2, gidx, didx);
    k_tail2<<<1, 256>>>(m2w1, m2b1, m2w2, m2b2, bn2g, bn2b, dout);
}